// round 16
// baseline (speedup 1.0000x reference)
#include <cuda_runtime.h>
#include <math.h>

// DuplicateRemovalLayer: x (B,16,3) fp32 -> out (B,16,3) fp32.
// Groups [0:6),[6:9),[9:12),[12:15): object j zeroed iff ANY later object i
// in its group has dR(i,j) < 0.05; inactive objects (pt<=0) use eta=phi=1e6
// sentinels (two inactive objects ARE mutual duplicates). Index 15 passthrough.
//
// LONG-BURST variant of the R15 pipeline: BPB=256 / 256 threads / 1 block/SM.
// Same NBUF=3, distance-2, one tile per wait-group (pipeline rate preserved —
// R13's failure mode avoided). Each tile is a 48KB contiguous read and a 48KB
// contiguous same-direction write burst, halving chip-wide read<->write DRAM
// turnaround frequency (extension of the proven R8 lazy-writeback mechanism).
// Plain evict-normal STG.128 stores, conflict-free padded smem (PADV=13),
// sparse zero write-back, 2 __syncthreads per iteration.

#define THREADS 256
#define BPB     256            // batches per tile
#define FPB     48             // floats per batch
#define F4PB    12             // float4 per batch
#define PADV    13             // padded float4 per batch (odd mod 8)
#define NBUF    3
#define BUF_F4  (BPB * PADV)   // 3328 float4 per buffer
#define SMEM_BYTES (NBUF * BUF_F4 * 16)   // 159,744 B
#define BLOCKS_PER_SM 1

__device__ __forceinline__ void cp_async16(float4* smem_dst, const float4* gmem_src) {
    unsigned s = (unsigned)__cvta_generic_to_shared(smem_dst);
    asm volatile("cp.async.cg.shared.global [%0], [%1], 16;" :: "r"(s), "l"(gmem_src));
}
#define CP_COMMIT() asm volatile("cp.async.commit_group;" ::: "memory")
#define CP_WAIT1()  asm volatile("cp.async.wait_group 1;" ::: "memory")

__device__ __forceinline__ bool is_dup(float ei, float pi_, float ej, float pj) {
    const float TWOPI  = 6.28318530717958647692f;
    const float INV2PI = 0.15915494309189533577f;
    float deta = ei - ej;
    float d    = pi_ - pj;
    float dphi = fmaf(-TWOPI, rintf(d * INV2PI), d);   // wrapped; enters squared
    return fmaf(deta, deta, dphi * dphi) < 0.0025f;    // dr^2 < 0.05^2
}

template <int N>
__device__ __forceinline__ void remove_group(const float* E, const float* P,
                                             unsigned& keep, int s0) {
    #pragma unroll
    for (int i = 1; i < N; i++) {
        #pragma unroll
        for (int j = 0; j < i; j++) {
            if (is_dup(E[s0 + i], P[s0 + i], E[s0 + j], P[s0 + j]))
                keep &= ~(1u << (s0 + j));
        }
    }
}

__device__ __forceinline__ void prefetch_tile(const float4* __restrict__ in4,
                                              int tile, int ntiles, int B,
                                              float4* buf, int tid) {
    if (tile < ntiles) {
        int nvalid = min(BPB, B - tile * BPB);
        int nf4 = nvalid * F4PB;
        const float4* src = in4 + (long long)tile * (BPB * F4PB);
        #pragma unroll
        for (int k = 0; k < F4PB; k++) {
            int f = tid + k * THREADS;
            if (f < nf4) cp_async16(&buf[(f / F4PB) * PADV + (f % F4PB)], &src[f]);
        }
    }
}

__global__ __launch_bounds__(THREADS)
void dup_removal_kernel(const float* __restrict__ in, float* __restrict__ out,
                        int B, int ntiles) {
    extern __shared__ float4 s4[];
    float4* bufs[NBUF] = { s4, s4 + BUF_F4, s4 + 2 * BUF_F4 };

    const int tid = threadIdx.x;
    const int G = gridDim.x;
    const int bid = blockIdx.x;

    // Prologue: prefetch tiles bid, bid+G (one group each)
    prefetch_tile((const float4*)in, bid, ntiles, B, bufs[0], tid);
    CP_COMMIT();
    prefetch_tile((const float4*)in, bid + G, ntiles, B, bufs[1], tid);
    CP_COMMIT();

    int li = 0;
    for (int tile = bid; tile < ntiles; tile += G, li++) {
        float4* cur = bufs[li % NBUF];

        // Retire current tile's group (exactly one newer group in flight).
        CP_WAIT1();
        __syncthreads();   // (A) orders prev store phase before the prefetch
                           //     below that reuses its buffer

        // Prefetch 2 ahead — buffer (li+2)%3 was last read by the store phase
        // of iteration li-1, completed before (A). Empty groups near the tail
        // keep wait accounting exact.
        prefetch_tile((const float4*)in, tile + 2 * G, ntiles, B,
                      bufs[(li + 2) % NBUF], tid);
        CP_COMMIT();

        const int nvalid = min(BPB, B - tile * BPB);

        // ---- compute: one thread per batch; sparse zero write-back ----
        if (tid < nvalid) {
            float4* pb = cur + tid * PADV;
            float p[FPB];
            #pragma unroll
            for (int k = 0; k < F4PB; k++) {        // 12 LDS.128, conflict-free
                float4 v = pb[k];
                p[4*k] = v.x; p[4*k+1] = v.y; p[4*k+2] = v.z; p[4*k+3] = v.w;
            }

            float E[15], P[15];
            #pragma unroll
            for (int i = 0; i < 15; i++) {
                bool act = p[3*i] > 0.0f;
                E[i] = act ? p[3*i+1] : 1000000.0f;
                P[i] = act ? p[3*i+2] : 1000000.0f;
            }

            unsigned keep = 0x7FFFu;
            remove_group<6>(E, P, keep, 0);
            remove_group<3>(E, P, keep, 6);
            remove_group<3>(E, P, keep, 9);
            remove_group<3>(E, P, keep, 12);

            if (keep != 0x7FFFu) {
                float* ps = (float*)pb;
                #pragma unroll
                for (int i = 0; i < 15; i++) {
                    if (!(keep & (1u << i))) {
                        ps[3*i] = 0.0f; ps[3*i+1] = 0.0f; ps[3*i+2] = 0.0f;
                    }
                }
            }
        }
        __syncthreads();   // (B) zero-writes visible before cross-batch store reads

        // ---- store: 48KB contiguous plain STG.128 burst (evict-normal) ----
        {
            int nf4 = nvalid * F4PB;
            float4* dst = (float4*)out + (long long)tile * (BPB * F4PB);
            #pragma unroll
            for (int k = 0; k < F4PB; k++) {
                int f = tid + k * THREADS;
                if (f < nf4)
                    dst[f] = cur[(f / F4PB) * PADV + (f % F4PB)];
            }
        }
        // No trailing barrier: next iteration's (A) orders this store phase
        // before any prefetch that reuses cur.
    }
}

extern "C" void kernel_launch(void* const* d_in, const int* in_sizes, int n_in,
                              void* d_out, int out_size) {
    const float* x = (const float*)d_in[0];
    float* out = (float*)d_out;
    const int B = in_sizes[0] / FPB;
    const int ntiles = (B + BPB - 1) / BPB;

    cudaFuncSetAttribute(dup_removal_kernel,
                         cudaFuncAttributeMaxDynamicSharedMemorySize, SMEM_BYTES);

    int dev = 0, nsm = 148;
    cudaGetDevice(&dev);
    cudaDeviceGetAttribute(&nsm, cudaDevAttrMultiProcessorCount, dev);

    int grid = BLOCKS_PER_SM * nsm;     // 1 block/SM
    if (grid > ntiles) grid = ntiles;

    dup_removal_kernel<<<grid, THREADS, SMEM_BYTES>>>(x, out, B, ntiles);
}

// round 17
// speedup vs baseline: 1.0659x; 1.0659x over previous
#include <cuda_runtime.h>
#include <math.h>

// DuplicateRemovalLayer: x (B,16,3) fp32 -> out (B,16,3) fp32.
// Groups [0:6),[6:9),[9:12),[12:15): object j zeroed iff ANY later object i
// in its group has dR(i,j) < 0.05; inactive objects (pt<=0) use eta=phi=1e6
// sentinels (two inactive objects ARE mutual duplicates). Index 15 passthrough.
//
// FINAL KERNEL — basin optimum of a 16-round search:
//   - persistent blocks, NBUF=3 smem ring, cp.async.cg prefetch distance 2
//   - 128 threads / 128 batches per tile, 2 blocks/SM (stream-count optimum:
//     1/4/8 blocks per SM all measured slower on the sustained harness)
//   - plain evict-normal STG.128 stores (L2 batches writebacks into long
//     same-direction DRAM runs; __stcs, evict-first reads, L2 hints, the
//     bulk-async/TMA engine, and longer bursts all measured worse)
//   - conflict-free padded smem (PADV=13 float4, odd mod 8)
//   - registers: rintf range-reduction for dphi, dr^2 threshold compare,
//     bitmask keep-state, sparse zero write-back (duplicates are rare)
//   - 2 __syncthreads per iteration (prefetch issued after the wait barrier,
//     making the trailing barrier redundant)
// Sustained-regime wall: ~66-67us ≈ 5.8 TB/s effective mixed R/W bandwidth.

#define THREADS 128
#define BPB     128            // batches per tile
#define FPB     48             // floats per batch
#define F4PB    12             // float4 per batch
#define PADV    13             // padded float4 per batch (odd mod 8)
#define NBUF    3
#define BUF_F4  (BPB * PADV)   // 1664 float4 per buffer
#define SMEM_BYTES (NBUF * BUF_F4 * 16)   // 79,872 B
#define BLOCKS_PER_SM 2

__device__ __forceinline__ void cp_async16(float4* smem_dst, const float4* gmem_src) {
    unsigned s = (unsigned)__cvta_generic_to_shared(smem_dst);
    asm volatile("cp.async.cg.shared.global [%0], [%1], 16;" :: "r"(s), "l"(gmem_src));
}
#define CP_COMMIT() asm volatile("cp.async.commit_group;" ::: "memory")
#define CP_WAIT1()  asm volatile("cp.async.wait_group 1;" ::: "memory")

__device__ __forceinline__ bool is_dup(float ei, float pi_, float ej, float pj) {
    const float TWOPI  = 6.28318530717958647692f;
    const float INV2PI = 0.15915494309189533577f;
    float deta = ei - ej;
    float d    = pi_ - pj;
    float dphi = fmaf(-TWOPI, rintf(d * INV2PI), d);   // wrapped; enters squared
    return fmaf(deta, deta, dphi * dphi) < 0.0025f;    // dr^2 < 0.05^2
}

template <int N>
__device__ __forceinline__ void remove_group(const float* E, const float* P,
                                             unsigned& keep, int s0) {
    #pragma unroll
    for (int i = 1; i < N; i++) {
        #pragma unroll
        for (int j = 0; j < i; j++) {
            if (is_dup(E[s0 + i], P[s0 + i], E[s0 + j], P[s0 + j]))
                keep &= ~(1u << (s0 + j));
        }
    }
}

__device__ __forceinline__ void prefetch_tile(const float4* __restrict__ in4,
                                              int tile, int ntiles, int B,
                                              float4* buf, int tid) {
    if (tile < ntiles) {
        int nvalid = min(BPB, B - tile * BPB);
        int nf4 = nvalid * F4PB;
        const float4* src = in4 + (long long)tile * (BPB * F4PB);
        #pragma unroll
        for (int k = 0; k < F4PB; k++) {
            int f = tid + k * THREADS;
            if (f < nf4) cp_async16(&buf[(f / F4PB) * PADV + (f % F4PB)], &src[f]);
        }
    }
}

__global__ __launch_bounds__(THREADS)
void dup_removal_kernel(const float* __restrict__ in, float* __restrict__ out,
                        int B, int ntiles) {
    extern __shared__ float4 s4[];
    float4* bufs[NBUF] = { s4, s4 + BUF_F4, s4 + 2 * BUF_F4 };

    const int tid = threadIdx.x;
    const int G = gridDim.x;
    const int bid = blockIdx.x;

    // Prologue: prefetch tiles bid, bid+G (one group each)
    prefetch_tile((const float4*)in, bid, ntiles, B, bufs[0], tid);
    CP_COMMIT();
    prefetch_tile((const float4*)in, bid + G, ntiles, B, bufs[1], tid);
    CP_COMMIT();

    int li = 0;
    for (int tile = bid; tile < ntiles; tile += G, li++) {
        float4* cur = bufs[li % NBUF];

        // Retire current tile's group (exactly one newer group in flight).
        CP_WAIT1();
        __syncthreads();   // (A) orders prev store phase before the prefetch
                           //     below that reuses its buffer

        // Prefetch 2 ahead — buffer (li+2)%3 was last read by the store phase
        // of iteration li-1, completed before (A). Empty groups near the tail
        // keep wait accounting exact.
        prefetch_tile((const float4*)in, tile + 2 * G, ntiles, B,
                      bufs[(li + 2) % NBUF], tid);
        CP_COMMIT();

        const int nvalid = min(BPB, B - tile * BPB);

        // ---- compute: one thread per batch; sparse zero write-back ----
        if (tid < nvalid) {
            float4* pb = cur + tid * PADV;
            float p[FPB];
            #pragma unroll
            for (int k = 0; k < F4PB; k++) {        // 12 LDS.128, conflict-free
                float4 v = pb[k];
                p[4*k] = v.x; p[4*k+1] = v.y; p[4*k+2] = v.z; p[4*k+3] = v.w;
            }

            float E[15], P[15];
            #pragma unroll
            for (int i = 0; i < 15; i++) {
                bool act = p[3*i] > 0.0f;
                E[i] = act ? p[3*i+1] : 1000000.0f;
                P[i] = act ? p[3*i+2] : 1000000.0f;
            }

            unsigned keep = 0x7FFFu;
            remove_group<6>(E, P, keep, 0);    // jets
            remove_group<3>(E, P, keep, 6);    // electrons
            remove_group<3>(E, P, keep, 9);    // muons
            remove_group<3>(E, P, keep, 12);   // photons

            if (keep != 0x7FFFu) {             // duplicates rare: almost never taken
                float* ps = (float*)pb;
                #pragma unroll
                for (int i = 0; i < 15; i++) {
                    if (!(keep & (1u << i))) {
                        ps[3*i] = 0.0f; ps[3*i+1] = 0.0f; ps[3*i+2] = 0.0f;
                    }
                }
            }
        }
        __syncthreads();   // (B) zero-writes visible before cross-batch store reads

        // ---- store: padded smem -> coalesced plain STG.128 (evict-normal) ----
        {
            int nf4 = nvalid * F4PB;
            float4* dst = (float4*)out + (long long)tile * (BPB * F4PB);
            #pragma unroll
            for (int k = 0; k < F4PB; k++) {
                int f = tid + k * THREADS;
                if (f < nf4)
                    dst[f] = cur[(f / F4PB) * PADV + (f % F4PB)];
            }
        }
        // No trailing barrier: next iteration's (A) orders this store phase
        // before any prefetch that reuses cur.
    }
}

extern "C" void kernel_launch(void* const* d_in, const int* in_sizes, int n_in,
                              void* d_out, int out_size) {
    const float* x = (const float*)d_in[0];
    float* out = (float*)d_out;
    const int B = in_sizes[0] / FPB;
    const int ntiles = (B + BPB - 1) / BPB;

    cudaFuncSetAttribute(dup_removal_kernel,
                         cudaFuncAttributeMaxDynamicSharedMemorySize, SMEM_BYTES);

    int dev = 0, nsm = 148;
    cudaGetDevice(&dev);
    cudaDeviceGetAttribute(&nsm, cudaDevAttrMultiProcessorCount, dev);

    int grid = BLOCKS_PER_SM * nsm;     // 2 blocks/SM (measured optimum)
    if (grid > ntiles) grid = ntiles;

    dup_removal_kernel<<<grid, THREADS, SMEM_BYTES>>>(x, out, B, ntiles);
}